// round 17
// baseline (speedup 1.0000x reference)
#include <cuda_runtime.h>
#include <cuda_bf16.h>
#include <cstdint>

// WideAndDeepModel fused v7, sm_103a via portable PTX (compute_103).
// Deep MLP on tensor cores through mma.sync.m16n8k16 bf16 (HMMA), fp32 accum,
// 3-term split precision (AhBh + AhBl + AlBh). 128 CTAs x 512 threads, one
// 128-row tile per CTA. Activations fp32 in SMEM, split to bf16 on the fly;
// weights prepacked in SMEM as bf16 hi/lo [n][k] rows (BN folded).
// No tcgen05 / no mbarrier: plain __syncthreads phases.

#define THREADS 512
#define GRID    128
#define XSS     178          // xs stride (floats): even (LDS.64 align), bank step 18

// ---- SMEM byte offsets ----
#define SM_B1S   0           // 128 f32
#define SM_B2S   512         // 64 f32
#define SM_B3S   768         // 32 f32
#define SM_W4S   896         // 32 f32
#define SM_IDS   1024        // 512 int
#define SM_W1H   3072        // [128n][180k] bf16, stride 360B = 46080
#define SM_W1L   49152
#define SM_W2H   95232       // [64n][136k] bf16, stride 272B = 17408
#define SM_W2L   112640
#define SM_W3H   130048      // [32n][72k] bf16, stride 144B = 4608
#define SM_W3L   134656
#define SM_XS    139264      // [128][178] f32 = 91136
#define SMEM_BYTES 230400    // <= 232448 limit

// h1: fp32 [128][134] in XS region (x dead). h2: [128][68] at SM_W1H (W1 dead).
// h3: [128][34] at SM_W1L.
#define H1S 134
#define H2S 68
#define H3S 34

__device__ __forceinline__ void splitp(float v0, float v1, uint32_t& hi, uint32_t& lo) {
    uint32_t h, l;
    asm("cvt.rn.bf16x2.f32 %0, %1, %2;" : "=r"(h) : "f"(v1), "f"(v0));  // low=v0, high=v1
    float r0 = v0 - __uint_as_float(h << 16);
    float r1 = v1 - __uint_as_float(h & 0xffff0000u);
    asm("cvt.rn.bf16x2.f32 %0, %1, %2;" : "=r"(l) : "f"(r1), "f"(r0));
    hi = h; lo = l;
}

__device__ __forceinline__ void mma_bf16(float* d, const uint32_t* a, uint32_t b0, uint32_t b1) {
    asm volatile(
        "mma.sync.aligned.m16n8k16.row.col.f32.bf16.bf16.f32 "
        "{%0,%1,%2,%3}, {%4,%5,%6,%7}, {%8,%9}, {%0,%1,%2,%3};"
        : "+f"(d[0]), "+f"(d[1]), "+f"(d[2]), "+f"(d[3])
        : "r"(a[0]), "r"(a[1]), "r"(a[2]), "r"(a[3]), "r"(b0), "r"(b1));
}

extern __shared__ char smc[];

__global__ void __launch_bounds__(THREADS, 1)
wd_fused_v7(const float* __restrict__ user,
            const float* __restrict__ price,
            const float* __restrict__ temporal,
            const float* __restrict__ item_emb,
            const float* __restrict__ cat_emb,
            const float* __restrict__ wide1,
            const float* __restrict__ wide2,
            const float* __restrict__ crossW,
            const int*   __restrict__ item_ids,
            const int*   __restrict__ cat_ids,
            const int*   __restrict__ wf1,
            const int*   __restrict__ wf2,
            const float* __restrict__ W1, const float* __restrict__ b1,
            const float* __restrict__ W2, const float* __restrict__ b2,
            const float* __restrict__ W3, const float* __restrict__ b3,
            const float* __restrict__ W4, const float* __restrict__ b4,
            const float* __restrict__ g1, const float* __restrict__ be1,
            const float* __restrict__ g2, const float* __restrict__ be2,
            const float* __restrict__ g3, const float* __restrict__ be3,
            float* __restrict__ out) {
    float* xs   = (float*)(smc + SM_XS);
    int*   idsm = (int*)(smc + SM_IDS);
    float* b1s  = (float*)(smc + SM_B1S);
    float* b2s  = (float*)(smc + SM_B2S);
    float* b3s  = (float*)(smc + SM_B3S);
    float* w4s  = (float*)(smc + SM_W4S);
    float* h1   = xs;                       // after L1, x is dead
    float* h2   = (float*)(smc + SM_W1H);   // after L1, W1 is dead
    float* h3   = (float*)(smc + SM_W1L);

    const int tid  = threadIdx.x;
    const int lane = tid & 31;
    const int w    = tid >> 5;
    const int q    = lane >> 2;          // fragment row/col within tile
    const int kp2  = 2 * (lane & 3);     // fragment k offset
    const float inv = rsqrtf(1.0f + 1e-5f);
    const int base = blockIdx.x * 128;

    // ---- ids ----
    {
        int which = tid >> 7, rr = tid & 127;
        const int* p = which == 0 ? item_ids : which == 1 ? cat_ids
                     : which == 2 ? wf1 : wf2;
        idsm[tid] = p[base + rr];
    }

    // ---- prepack weights: bf16 hi/lo, W^T[n][k], BN folded, zero-padded k ----
    for (int i = tid; i < 128 * 90; i += THREADS) {          // W1: k pad to 180
        int n = i / 90, kp = i - n * 90, k = 2 * kp;
        float s = g1[n] * inv;
        float v0 = (k < 164) ? W1[k * 128 + n] * s : 0.f;
        float v1 = (k + 1 < 164) ? W1[(k + 1) * 128 + n] * s : 0.f;
        uint32_t hi, lo;
        splitp(v0, v1, hi, lo);
        int off = n * 360 + 4 * kp;
        *(uint32_t*)(smc + SM_W1H + off) = hi;
        *(uint32_t*)(smc + SM_W1L + off) = lo;
    }
    for (int i = tid; i < 64 * 68; i += THREADS) {           // W2: k pad to 136
        int n = i / 68, kp = i - n * 68, k = 2 * kp;
        float s = g2[n] * inv;
        float v0 = (k < 128) ? W2[k * 64 + n] * s : 0.f;
        float v1 = (k + 1 < 128) ? W2[(k + 1) * 64 + n] * s : 0.f;
        uint32_t hi, lo;
        splitp(v0, v1, hi, lo);
        int off = n * 272 + 4 * kp;
        *(uint32_t*)(smc + SM_W2H + off) = hi;
        *(uint32_t*)(smc + SM_W2L + off) = lo;
    }
    for (int i = tid; i < 32 * 36; i += THREADS) {           // W3: k pad to 72
        int n = i / 36, kp = i - n * 36, k = 2 * kp;
        float s = g3[n] * inv;
        float v0 = (k < 64) ? W3[k * 32 + n] * s : 0.f;
        float v1 = (k + 1 < 64) ? W3[(k + 1) * 32 + n] * s : 0.f;
        uint32_t hi, lo;
        splitp(v0, v1, hi, lo);
        int off = n * 144 + 4 * kp;
        *(uint32_t*)(smc + SM_W3H + off) = hi;
        *(uint32_t*)(smc + SM_W3L + off) = lo;
    }
    if (tid < 128) b1s[tid] = b1[tid] * (g1[tid] * inv) + be1[tid];
    if (tid < 64)  b2s[tid] = b2[tid] * (g2[tid] * inv) + be2[tid];
    if (tid < 32) {
        b3s[tid] = b3[tid] * (g3[tid] * inv) + be3[tid];
        w4s[tid] = W4[tid];
    }
    const float b4v = b4[0];
    __syncthreads();

    // ---- wide prefetch ----
    float wv1 = 0.f, wv2 = 0.f, wcx = 0.f;
    if (tid < 128) {
        int f1 = idsm[256 + tid], f2 = idsm[384 + tid];
        wv1 = wide1[f1];
        wv2 = wide2[f2];
        wcx = crossW[(long long)f1 * 10000 + f2];
    }

    // ---- gather x row-major: xs[r][0..163], zero-pad [164..177] ----
#pragma unroll
    for (int i = 0; i < 16; ++i) {
        int idx = tid + i * 512, r = idx >> 6, c = idx & 63;
        xs[r * XSS + c] = user[(base + r) * 64 + c];
    }
#pragma unroll
    for (int i = 0; i < 16; ++i) {
        int idx = tid + i * 512, r = idx >> 6, c = idx & 63;
        xs[r * XSS + 64 + c] = item_emb[(long long)idsm[r] * 64 + c];
    }
#pragma unroll
    for (int i = 0; i < 8; ++i) {
        int idx = tid + i * 512, r = idx >> 5, c = idx & 31;
        xs[r * XSS + 128 + c] = cat_emb[idsm[128 + r] * 32 + c];
    }
    if (tid < 256) {
        int r = tid >> 1, c = tid & 1;
        xs[r * XSS + 160 + c] = price[(base + r) * 2 + c];
        xs[r * XSS + 162 + c] = temporal[(base + r) * 2 + c];
    }
#pragma unroll
    for (int i = 0; i < 4; ++i) {          // zero pad cols 164..177 (14 cols)
        int idx = tid + i * 512;
        if (idx < 128 * 14) {
            int r = idx / 14, c = 164 + idx - r * 14;
            xs[r * XSS + c] = 0.f;
        }
    }
    __syncthreads();

    // ================= L1: [128x176] @ W1^T -> [128x128] =================
    // warp tile: 2 m-tiles x 4 n-tiles.  mp = w&3 (m-tiles 2mp,2mp+1),
    // nq = w>>2 (n-tiles 4nq..4nq+3, cols 32nq..32nq+31)
    const int mp = w & 3;
    const int nq = w >> 2;
    float acc1[2][4][4];
#pragma unroll
    for (int a = 0; a < 2; ++a)
#pragma unroll
        for (int b_ = 0; b_ < 4; ++b_)
#pragma unroll
            for (int c = 0; c < 4; ++c) acc1[a][b_][c] = 0.f;

#pragma unroll
    for (int kc = 0; kc < 11; ++kc) {
        const int k0 = 16 * kc;
        uint32_t ah[2][4], al[2][4];
#pragma unroll
        for (int mi = 0; mi < 2; ++mi) {
            const float* xr = xs + (32 * mp + 16 * mi + q) * XSS;
            float2 p0 = *(const float2*)(xr + k0 + kp2);
            float2 p1 = *(const float2*)(xr + k0 + 8 + kp2);
            float2 p2 = *(const float2*)(xr + 8 * XSS + k0 + kp2);
            float2 p3 = *(const float2*)(xr + 8 * XSS + k0 + 8 + kp2);
            splitp(p0.x, p0.y, ah[mi][0], al[mi][0]);   // a0: row q,   k
            splitp(p2.x, p2.y, ah[mi][1], al[mi][1]);   // a1: row q+8, k
            splitp(p1.x, p1.y, ah[mi][2], al[mi][2]);   // a2: row q,   k+8
            splitp(p3.x, p3.y, ah[mi][3], al[mi][3]);   // a3: row q+8, k+8
        }
#pragma unroll
        for (int nt = 0; nt < 4; ++nt) {
            const char* wb = smc + SM_W1H + (32 * nq + 8 * nt + q) * 360 + (k0 + kp2) * 2;
            uint32_t bh0 = *(const uint32_t*)wb;
            uint32_t bh1 = *(const uint32_t*)(wb + 16);
            uint32_t bl0 = *(const uint32_t*)(wb + (SM_W1L - SM_W1H));
            uint32_t bl1 = *(const uint32_t*)(wb + (SM_W1L - SM_W1H) + 16);
#pragma unroll
            for (int mi = 0; mi < 2; ++mi) {
                mma_bf16(acc1[mi][nt], ah[mi], bh0, bh1);
                mma_bf16(acc1[mi][nt], ah[mi], bl0, bl1);
                mma_bf16(acc1[mi][nt], al[mi], bh0, bh1);
            }
        }
    }
    __syncthreads();   // all warps done reading xs -> safe to overwrite with h1

    // ---- L1 epilogue: bias + relu -> h1 fp32 (stride 134, in xs region) ----
#pragma unroll
    for (int mi = 0; mi < 2; ++mi) {
        const int r0 = 32 * mp + 16 * mi + q;
#pragma unroll
        for (int nt = 0; nt < 4; ++nt) {
            const int c0 = 32 * nq + 8 * nt + kp2;
            float bb0 = b1s[c0], bb1 = b1s[c0 + 1];
            float2 v;
            v.x = fmaxf(acc1[mi][nt][0] + bb0, 0.f);
            v.y = fmaxf(acc1[mi][nt][1] + bb1, 0.f);
            *(float2*)(h1 + r0 * H1S + c0) = v;
            v.x = fmaxf(acc1[mi][nt][2] + bb0, 0.f);
            v.y = fmaxf(acc1[mi][nt][3] + bb1, 0.f);
            *(float2*)(h1 + (r0 + 8) * H1S + c0) = v;
        }
    }
    __syncthreads();

    // ================= L2: [128x128] @ W2^T -> [128x64] =================
    // warp tile: 2m x 2n. mp = w&3, nd = w>>2 (n-tiles 2nd,2nd+1; cols 16nd..)
    const int nd = w >> 2;
    float acc2[2][2][4];
#pragma unroll
    for (int a = 0; a < 2; ++a)
#pragma unroll
        for (int b_ = 0; b_ < 2; ++b_)
#pragma unroll
            for (int c = 0; c < 4; ++c) acc2[a][b_][c] = 0.f;

#pragma unroll
    for (int kc = 0; kc < 8; ++kc) {
        const int k0 = 16 * kc;
        uint32_t ah[2][4], al[2][4];
#pragma unroll
        for (int mi = 0; mi < 2; ++mi) {
            const float* xr = h1 + (32 * mp + 16 * mi + q) * H1S;
            float2 p0 = *(const float2*)(xr + k0 + kp2);
            float2 p1 = *(const float2*)(xr + k0 + 8 + kp2);
            float2 p2 = *(const float2*)(xr + 8 * H1S + k0 + kp2);
            float2 p3 = *(const float2*)(xr + 8 * H1S + k0 + 8 + kp2);
            splitp(p0.x, p0.y, ah[mi][0], al[mi][0]);
            splitp(p2.x, p2.y, ah[mi][1], al[mi][1]);
            splitp(p1.x, p1.y, ah[mi][2], al[mi][2]);
            splitp(p3.x, p3.y, ah[mi][3], al[mi][3]);
        }
#pragma unroll
        for (int nt = 0; nt < 2; ++nt) {
            const char* wb = smc + SM_W2H + (16 * nd + 8 * nt + q) * 272 + (k0 + kp2) * 2;
            uint32_t bh0 = *(const uint32_t*)wb;
            uint32_t bh1 = *(const uint32_t*)(wb + 16);
            uint32_t bl0 = *(const uint32_t*)(wb + (SM_W2L - SM_W2H));
            uint32_t bl1 = *(const uint32_t*)(wb + (SM_W2L - SM_W2H) + 16);
#pragma unroll
            for (int mi = 0; mi < 2; ++mi) {
                mma_bf16(acc2[mi][nt], ah[mi], bh0, bh1);
                mma_bf16(acc2[mi][nt], ah[mi], bl0, bl1);
                mma_bf16(acc2[mi][nt], al[mi], bh0, bh1);
            }
        }
    }
    // h2 region (old W1H) is disjoint from h1 and W2 -> store without pre-sync
#pragma unroll
    for (int mi = 0; mi < 2; ++mi) {
        const int r0 = 32 * mp + 16 * mi + q;
#pragma unroll
        for (int nt = 0; nt < 2; ++nt) {
            const int c0 = 16 * nd + 8 * nt + kp2;
            float bb0 = b2s[c0], bb1 = b2s[c0 + 1];
            float2 v;
            v.x = fmaxf(acc2[mi][nt][0] + bb0, 0.f);
            v.y = fmaxf(acc2[mi][nt][1] + bb1, 0.f);
            *(float2*)(h2 + r0 * H2S + c0) = v;
            v.x = fmaxf(acc2[mi][nt][2] + bb0, 0.f);
            v.y = fmaxf(acc2[mi][nt][3] + bb1, 0.f);
            *(float2*)(h2 + (r0 + 8) * H2S + c0) = v;
        }
    }
    __syncthreads();

    // ================= L3: [128x64] @ W3^T -> [128x32] =================
    // warp tile: 2m x 1n. mp = w&3, n-tile nd = w>>2 (cols 8nd..8nd+7)
    float acc3[2][4];
#pragma unroll
    for (int a = 0; a < 2; ++a)
#pragma unroll
        for (int c = 0; c < 4; ++c) acc3[a][c] = 0.f;

#pragma unroll
    for (int kc = 0; kc < 4; ++kc) {
        const int k0 = 16 * kc;
        uint32_t ah[2][4], al[2][4];
#pragma unroll
        for (int mi = 0; mi < 2; ++mi) {
            const float* xr = h2 + (32 * mp + 16 * mi + q) * H2S;
            float2 p0 = *(const float2*)(xr + k0 + kp2);
            float2 p1 = *(const float2*)(xr + k0 + 8 + kp2);
            float2 p2 = *(const float2*)(xr + 8 * H2S + k0 + kp2);
            float2 p3 = *(const float2*)(xr + 8 * H2S + k0 + 8 + kp2);
            splitp(p0.x, p0.y, ah[mi][0], al[mi][0]);
            splitp(p2.x, p2.y, ah[mi][1], al[mi][1]);
            splitp(p1.x, p1.y, ah[mi][2], al[mi][2]);
            splitp(p3.x, p3.y, ah[mi][3], al[mi][3]);
        }
        const char* wb = smc + SM_W3H + (8 * nd + q) * 144 + (k0 + kp2) * 2;
        uint32_t bh0 = *(const uint32_t*)wb;
        uint32_t bh1 = *(const uint32_t*)(wb + 16);
        uint32_t bl0 = *(const uint32_t*)(wb + (SM_W3L - SM_W3H));
        uint32_t bl1 = *(const uint32_t*)(wb + (SM_W3L - SM_W3H) + 16);
#pragma unroll
        for (int mi = 0; mi < 2; ++mi) {
            mma_bf16(acc3[mi], ah[mi], bh0, bh1);
            mma_bf16(acc3[mi], ah[mi], bl0, bl1);
            mma_bf16(acc3[mi], al[mi], bh0, bh1);
        }
    }
    // h3 region (old W1L) disjoint from h2/W3 -> store without pre-sync
#pragma unroll
    for (int mi = 0; mi < 2; ++mi) {
        const int r0 = 32 * mp + 16 * mi + q;
        const int c0 = 8 * nd + kp2;
        float bb0 = b3s[c0], bb1 = b3s[c0 + 1];
        float2 v;
        v.x = fmaxf(acc3[mi][0] + bb0, 0.f);
        v.y = fmaxf(acc3[mi][1] + bb1, 0.f);
        *(float2*)(h3 + r0 * H3S + c0) = v;
        v.x = fmaxf(acc3[mi][2] + bb0, 0.f);
        v.y = fmaxf(acc3[mi][3] + bb1, 0.f);
        *(float2*)(h3 + (r0 + 8) * H3S + c0) = v;
    }
    __syncthreads();

    // ---- L4 (32->1) + wide; one thread per row ----
    if (tid < 128) {
        const float* hr = h3 + tid * H3S;
        float s0 = 0.f, s1 = 0.f, s2 = 0.f, s3 = 0.f;
#pragma unroll
        for (int k = 0; k < 32; k += 4) {
            s0 = fmaf(hr[k],     w4s[k],     s0);
            s1 = fmaf(hr[k + 1], w4s[k + 1], s1);
            s2 = fmaf(hr[k + 2], w4s[k + 2], s2);
            s3 = fmaf(hr[k + 3], w4s[k + 3], s3);
        }
        out[base + tid] = (s0 + s1) + (s2 + s3) + b4v + wv1 + wv2 + wcx;
    }
}

extern "C" void kernel_launch(void* const* d_in, const int* in_sizes, int n_in,
                              void* d_out, int out_size) {
    (void)in_sizes; (void)n_in; (void)out_size;
    static bool attr_set = false;
    if (!attr_set) {
        cudaFuncSetAttribute(wd_fused_v7,
                             cudaFuncAttributeMaxDynamicSharedMemorySize, SMEM_BYTES);
        attr_set = true;
    }
    wd_fused_v7<<<GRID, THREADS, SMEM_BYTES>>>(
        (const float*)d_in[0], (const float*)d_in[1], (const float*)d_in[2],
        (const float*)d_in[3], (const float*)d_in[4], (const float*)d_in[5],
        (const float*)d_in[6], (const float*)d_in[7],
        (const int*)d_in[8], (const int*)d_in[9], (const int*)d_in[10],
        (const int*)d_in[11],
        (const float*)d_in[12], (const float*)d_in[13],
        (const float*)d_in[14], (const float*)d_in[15],
        (const float*)d_in[16], (const float*)d_in[17],
        (const float*)d_in[18], (const float*)d_in[19],
        (const float*)d_in[20], (const float*)d_in[21],
        (const float*)d_in[22], (const float*)d_in[23],
        (const float*)d_in[24], (const float*)d_in[25],
        (float*)d_out);
}